// round 14
// baseline (speedup 1.0000x reference)
#include <cuda_runtime.h>
#include <cuda_bf16.h>
#include <cstdint>

#define TT 16          // time steps
#define BB 16          // batch
#define CC 256         // channels C (and Cc)
#define DD 512         // 2*C
#define HW 1024        // H*W

// ---------------------------------------------------------------------------
// Single fused kernel, one launch. Grid = 4096 blocks x 512 threads; block
// owns SIXTEEN consecutive channels of one (t,b) slice. Same per-thread film
// shape as the proven kernel (8 hoisted float4 loads, MLP=8), but the
// LIF/GEMM preamble now runs once per 16 channels instead of once per 8 —
// half the redundant preamble work chip-wide.
//
// Phase A: threads 0..255: LIF scan for (b, cc); 16 independent cond loads
//          (L2-resident after first wave), register recurrence, keep spike
//          at this block's t. Spikes -> smem.
// Phase B: all 512 threads: 32 dot products (16 gamma + 16 beta rows),
//          16 lanes each; conflict-free smem + coalesced W, shfl reduce.
// Phase C: film body: 8 float4 loads at stride 512 (rows j*2 + tid/256),
//          params broadcast from smem, streaming stores.
// ---------------------------------------------------------------------------
__global__ void __launch_bounds__(512) fused_kernel(
    const float4* __restrict__ x,
    const float*  __restrict__ cond,
    const float*  __restrict__ Wm,
    const float*  __restrict__ bias,
    float4*       __restrict__ out) {
    __shared__ float s_sp[CC];      // spikes at this block's t
    __shared__ float s_par[32];     // 16 gamma | 16 beta

    int tid  = threadIdx.x;
    unsigned row0 = blockIdx.x * 16;        // first channel-row of block
    unsigned tb   = row0 >> 8;              // t*BB + b
    unsigned c0   = row0 & (CC - 1);        // 16-aligned channel offset
    int t = (int)(tb >> 4);                 // this block's time step
    int b = (int)(tb & 15);

    // --- Phase A: LIF scan (threads 0..255, one per cc) ---
    if (tid < CC) {
        int cc = tid;
        float xv[TT];
#pragma unroll
        for (int tp = 0; tp < TT; ++tp)     // independent loads, MLP=16
            xv[tp] = cond[(tp * BB + b) * CC + cc];
        float v = 0.0f, s_t = 0.0f;
#pragma unroll
        for (int tp = 0; tp < TT; ++tp) {
            v = v + (xv[tp] - v) * 0.5f;             // charge (TAU=2)
            float s = (v >= 1.0f) ? 1.0f : 0.0f;     // fire
            if (tp == t) s_t = s;                    // predicated select
            v = (1.0f - s) * v;                      // hard reset
        }
        s_sp[cc] = s_t;
    }
    __syncthreads();

    // --- Phase B: 32 dot products (16 gamma rows, 16 beta rows) ---
    {
        int o  = tid >> 4;                  // output 0..31
        int ch = tid & 15;                  // k-chunk lane 0..15
        int d  = (o < 16) ? (int)(c0 + o) : (int)(CC + c0 + (o - 16));
        const float* __restrict__ wr = Wm + (size_t)d * CC;

        float a = 0.0f;
#pragma unroll
        for (int i = 0; i < 16; ++i) {
            int k = i * 16 + ch;            // conflict-free smem, coalesced W
            a = fmaf(s_sp[k], wr[k], a);
        }
#pragma unroll
        for (int m = 8; m >= 1; m >>= 1)    // reduce within 16-lane group
            a += __shfl_xor_sync(0xFFFFFFFFu, a, m);
        if (ch == 0) s_par[o] = a + bias[d];
    }
    __syncthreads();

    // --- Phase C: film body. Thread covers 8 float4 at stride 512.
    //     idx j -> channel row (j*2 + tid/256); params from smem. ---
    int hi = tid >> 8;                      // 0 or 1: which row of each pair
    size_t base = (size_t)row0 * 256 + tid; // row0*256 + tid, stride 512

    float4 v0 = x[base];
    float4 v1 = x[base + 512];
    float4 v2 = x[base + 1024];
    float4 v3 = x[base + 1536];
    float4 v4 = x[base + 2048];
    float4 v5 = x[base + 2560];
    float4 v6 = x[base + 3072];
    float4 v7 = x[base + 3584];

    float g0 = 1.0f + s_par[hi],      b0 = s_par[16 + hi];
    float g1 = 1.0f + s_par[2 + hi],  b1 = s_par[18 + hi];
    float g2 = 1.0f + s_par[4 + hi],  b2 = s_par[20 + hi];
    float g3 = 1.0f + s_par[6 + hi],  b3 = s_par[22 + hi];
    float g4 = 1.0f + s_par[8 + hi],  b4 = s_par[24 + hi];
    float g5 = 1.0f + s_par[10 + hi], b5 = s_par[26 + hi];
    float g6 = 1.0f + s_par[12 + hi], b6 = s_par[28 + hi];
    float g7 = 1.0f + s_par[14 + hi], b7 = s_par[30 + hi];

    float4 o;
    o.x = fmaf(g0, v0.x, b0); o.y = fmaf(g0, v0.y, b0);
    o.z = fmaf(g0, v0.z, b0); o.w = fmaf(g0, v0.w, b0);
    __stcs(&out[base], o);
    o.x = fmaf(g1, v1.x, b1); o.y = fmaf(g1, v1.y, b1);
    o.z = fmaf(g1, v1.z, b1); o.w = fmaf(g1, v1.w, b1);
    __stcs(&out[base + 512], o);
    o.x = fmaf(g2, v2.x, b2); o.y = fmaf(g2, v2.y, b2);
    o.z = fmaf(g2, v2.z, b2); o.w = fmaf(g2, v2.w, b2);
    __stcs(&out[base + 1024], o);
    o.x = fmaf(g3, v3.x, b3); o.y = fmaf(g3, v3.y, b3);
    o.z = fmaf(g3, v3.z, b3); o.w = fmaf(g3, v3.w, b3);
    __stcs(&out[base + 1536], o);
    o.x = fmaf(g4, v4.x, b4); o.y = fmaf(g4, v4.y, b4);
    o.z = fmaf(g4, v4.z, b4); o.w = fmaf(g4, v4.w, b4);
    __stcs(&out[base + 2048], o);
    o.x = fmaf(g5, v5.x, b5); o.y = fmaf(g5, v5.y, b5);
    o.z = fmaf(g5, v5.z, b5); o.w = fmaf(g5, v5.w, b5);
    __stcs(&out[base + 2560], o);
    o.x = fmaf(g6, v6.x, b6); o.y = fmaf(g6, v6.y, b6);
    o.z = fmaf(g6, v6.z, b6); o.w = fmaf(g6, v6.w, b6);
    __stcs(&out[base + 3072], o);
    o.x = fmaf(g7, v7.x, b7); o.y = fmaf(g7, v7.y, b7);
    o.z = fmaf(g7, v7.z, b7); o.w = fmaf(g7, v7.w, b7);
    __stcs(&out[base + 3584], o);
}

// ---------------------------------------------------------------------------
extern "C" void kernel_launch(void* const* d_in, const int* in_sizes, int n_in,
                              void* d_out, int out_size) {
    const float* x    = (const float*)d_in[0];   // [T,B,C,H,W]
    const float* cond = (const float*)d_in[1];   // [T,B,Cc]
    const float* Wm   = (const float*)d_in[2];   // [2C,Cc]
    const float* bias = (const float*)d_in[3];   // [2C]
    float* out = (float*)d_out;

    fused_kernel<<<TT * BB * CC / 16, 512>>>(
        (const float4*)x, cond, Wm, bias, (float4*)out);
}

// round 15
// speedup vs baseline: 1.0339x; 1.0339x over previous
#include <cuda_runtime.h>
#include <cuda_bf16.h>
#include <cstdint>

#define TT 16          // time steps
#define BB 16          // batch
#define CC 256         // channels C (and Cc)
#define DD 512         // 2*C
#define HW 1024        // H*W

// ---------------------------------------------------------------------------
// Single fused kernel, one launch. Grid = 8192 blocks x 256 threads; block
// owns 8 consecutive channels of one (t,b) slice -- the proven 40-reg shape
// that keeps all 8 float4 loads in flight (MLP=8). Plain loads (saves the 4
// regs __ldcs cost), streaming stores (__stcs: out is write-once).
//
// Phase A: block-local LIF scan; thread cc loads cond[(t',b,cc)] for all 16
//          t' (independent, L2-resident after first wave), runs the
//          recurrence in registers, keeps the spike at THIS block's t.
// Phase B: 16 params = 16 dot products of length 256; 16 lanes per output,
//          conflict-free smem + coalesced W, 4-stage shfl reduce.
// Phase C: MLP=8 FiLM body, params broadcast from smem.
// ---------------------------------------------------------------------------
__global__ void __launch_bounds__(256) fused_kernel(
    const float4* __restrict__ x,
    const float*  __restrict__ cond,
    const float*  __restrict__ Wm,
    const float*  __restrict__ bias,
    float4*       __restrict__ out) {
    __shared__ float s_sp[CC];      // spikes at this block's t
    __shared__ float s_par[16];     // 8 gamma | 8 beta

    int tid  = threadIdx.x;
    unsigned row0 = blockIdx.x * 8;         // first channel-row
    unsigned tb   = row0 >> 8;              // t*BB + b
    unsigned c0   = row0 & (CC - 1);
    int t = (int)(tb >> 4);                 // this block's time step
    int b = (int)(tb & 15);

    // --- Phase A: LIF scan for (b, cc=tid); keep spike at step t ---
    {
        int cc = tid;
        float xv[TT];
#pragma unroll
        for (int tp = 0; tp < TT; ++tp)     // independent loads, MLP=16
            xv[tp] = cond[(tp * BB + b) * CC + cc];
        float v = 0.0f, s_t = 0.0f;
#pragma unroll
        for (int tp = 0; tp < TT; ++tp) {
            v = v + (xv[tp] - v) * 0.5f;             // charge (TAU=2)
            float s = (v >= 1.0f) ? 1.0f : 0.0f;     // fire
            if (tp == t) s_t = s;                    // predicated select
            v = (1.0f - s) * v;                      // hard reset
        }
        s_sp[cc] = s_t;
    }
    __syncthreads();

    // --- Phase B: 16 dot products (8 gamma rows, 8 beta rows) ---
    {
        int o  = tid >> 4;                  // output 0..15
        int ch = tid & 15;                  // k-chunk lane 0..15
        int d  = (o < 8) ? (int)(c0 + o) : (int)(CC + c0 + (o - 8));
        const float* __restrict__ wr = Wm + (size_t)d * CC;

        float a = 0.0f;
#pragma unroll
        for (int i = 0; i < 16; ++i) {
            int k = i * 16 + ch;            // conflict-free smem, coalesced W
            a = fmaf(s_sp[k], wr[k], a);
        }
#pragma unroll
        for (int m = 8; m >= 1; m >>= 1)    // reduce within 16-lane group
            a += __shfl_xor_sync(0xFFFFFFFFu, a, m);
        if (ch == 0) s_par[o] = a + bias[d];
    }
    __syncthreads();

    // --- Phase C: FiLM body (8 hoisted float4 loads, streaming stores) ---
    size_t base = (size_t)row0 * 256 + tid;

    float4 v0 = x[base];
    float4 v1 = x[base + 256];
    float4 v2 = x[base + 512];
    float4 v3 = x[base + 768];
    float4 v4 = x[base + 1024];
    float4 v5 = x[base + 1280];
    float4 v6 = x[base + 1536];
    float4 v7 = x[base + 1792];

    float g0 = 1.0f + s_par[0], g1 = 1.0f + s_par[1];
    float g2 = 1.0f + s_par[2], g3 = 1.0f + s_par[3];
    float g4 = 1.0f + s_par[4], g5 = 1.0f + s_par[5];
    float g6 = 1.0f + s_par[6], g7 = 1.0f + s_par[7];
    float b0 = s_par[8],  b1 = s_par[9],  b2 = s_par[10], b3 = s_par[11];
    float b4 = s_par[12], b5 = s_par[13], b6 = s_par[14], b7 = s_par[15];

    float4 o;
    o.x = fmaf(g0, v0.x, b0); o.y = fmaf(g0, v0.y, b0);
    o.z = fmaf(g0, v0.z, b0); o.w = fmaf(g0, v0.w, b0);
    __stcs(&out[base], o);
    o.x = fmaf(g1, v1.x, b1); o.y = fmaf(g1, v1.y, b1);
    o.z = fmaf(g1, v1.z, b1); o.w = fmaf(g1, v1.w, b1);
    __stcs(&out[base + 256], o);
    o.x = fmaf(g2, v2.x, b2); o.y = fmaf(g2, v2.y, b2);
    o.z = fmaf(g2, v2.z, b2); o.w = fmaf(g2, v2.w, b2);
    __stcs(&out[base + 512], o);
    o.x = fmaf(g3, v3.x, b3); o.y = fmaf(g3, v3.y, b3);
    o.z = fmaf(g3, v3.z, b3); o.w = fmaf(g3, v3.w, b3);
    __stcs(&out[base + 768], o);
    o.x = fmaf(g4, v4.x, b4); o.y = fmaf(g4, v4.y, b4);
    o.z = fmaf(g4, v4.z, b4); o.w = fmaf(g4, v4.w, b4);
    __stcs(&out[base + 1024], o);
    o.x = fmaf(g5, v5.x, b5); o.y = fmaf(g5, v5.y, b5);
    o.z = fmaf(g5, v5.z, b5); o.w = fmaf(g5, v5.w, b5);
    __stcs(&out[base + 1280], o);
    o.x = fmaf(g6, v6.x, b6); o.y = fmaf(g6, v6.y, b6);
    o.z = fmaf(g6, v6.z, b6); o.w = fmaf(g6, v6.w, b6);
    __stcs(&out[base + 1536], o);
    o.x = fmaf(g7, v7.x, b7); o.y = fmaf(g7, v7.y, b7);
    o.z = fmaf(g7, v7.z, b7); o.w = fmaf(g7, v7.w, b7);
    __stcs(&out[base + 1792], o);
}

// ---------------------------------------------------------------------------
extern "C" void kernel_launch(void* const* d_in, const int* in_sizes, int n_in,
                              void* d_out, int out_size) {
    const float* x    = (const float*)d_in[0];   // [T,B,C,H,W]
    const float* cond = (const float*)d_in[1];   // [T,B,Cc]
    const float* Wm   = (const float*)d_in[2];   // [2C,Cc]
    const float* bias = (const float*)d_in[3];   // [2C]
    float* out = (float*)d_out;

    fused_kernel<<<TT * BB * CC / 8, 256>>>(
        (const float4*)x, cond, Wm, bias, (float4*)out);
}